// round 5
// baseline (speedup 1.0000x reference)
#include <cuda_runtime.h>
#include <math.h>

#define BB 8
#define NN 8192
#define SS 8
#define MROWS (BB * NN)          // 65536 tokens
#define DIN 64
#define DH  128                  // hidden
#define DOUT 64
#define ABC_COLS 384             // [A(128) | B(128) | C(128)]

// Scratch: ABC[m][0:128]=x@W1a (+b1), [128:256]=x@W1b, [256:384]=x@W1c  (96 MB)
__device__ float g_ABC[(size_t)MROWS * ABC_COLS];

// tanh-form GELU with HW MUFU.TANH. Model err ~6e-5 abs, tanh.approx ~5e-4 max.
__device__ __forceinline__ float gelu_fast(float x) {
    float x2 = x * x;
    float u  = x * (0.7978845608028654f + 0.035677408136300125f * x2);
    float t;
    asm("tanh.approx.f32 %0, %1;" : "=f"(t) : "f"(u));
    return 0.5f * x * (1.0f + t);
}

// ---------------------------------------------------------------------------
// Kernel 1: ABC = X (65536 x 64) @ W1-as-(64 x 384)   [+ b1 on part 0]
//   2 K-stages of 32; kb=1 tiles prefetched into registers during kb=0 compute.
// ---------------------------------------------------------------------------
__global__ __launch_bounds__(256, 2) void k1_gemm(const float* __restrict__ X,
                                                  const float* __restrict__ W1,
                                                  const float* __restrict__ b1)
{
    __shared__ float XsT[32][132];   // [k][row] transposed, padded
    __shared__ float Ws [32][128];   // [k][col_local]

    const int tid  = threadIdx.x;
    const int m0   = blockIdx.x * 128;
    const int part = blockIdx.y;           // 0..2

    // ---- stage 0 (kb=0) load straight to smem ----
    int xrow[4], xkq[4];
    #pragma unroll
    for (int i = 0; i < 4; i++) {
        int lin = tid + i * 256;           // 0..1023
        xrow[i] = lin >> 3;                // 0..127
        xkq[i]  = lin & 7;                 // 0..7
        float4 v = *(const float4*)&X[(size_t)(m0 + xrow[i]) * DIN + xkq[i] * 4];
        XsT[xkq[i] * 4 + 0][xrow[i]] = v.x;
        XsT[xkq[i] * 4 + 1][xrow[i]] = v.y;
        XsT[xkq[i] * 4 + 2][xrow[i]] = v.z;
        XsT[xkq[i] * 4 + 3][xrow[i]] = v.w;
    }
    int wk[4], wcq[4];
    #pragma unroll
    for (int i = 0; i < 4; i++) {
        int lin = tid + i * 256;
        wk[i]  = lin >> 5;                 // 0..31
        wcq[i] = lin & 31;                 // 0..31
        *(float4*)&Ws[wk[i]][wcq[i] * 4] =
            *(const float4*)&W1[(size_t)(part * 64 + wk[i]) * DH + wcq[i] * 4];
    }

    // ---- prefetch stage 1 (kb=1) into registers ----
    float4 xr[4], wr[4];
    #pragma unroll
    for (int i = 0; i < 4; i++)
        xr[i] = *(const float4*)&X[(size_t)(m0 + xrow[i]) * DIN + 32 + xkq[i] * 4];
    #pragma unroll
    for (int i = 0; i < 4; i++)
        wr[i] = *(const float4*)&W1[(size_t)(part * 64 + 32 + wk[i]) * DH + wcq[i] * 4];

    __syncthreads();

    const int tx = tid & 15;
    const int ty = tid >> 4;
    float acc[8][8];
    #pragma unroll
    for (int i = 0; i < 8; i++)
        #pragma unroll
        for (int j = 0; j < 8; j++) acc[i][j] = 0.0f;

    // ---- compute kb=0 ----
    #pragma unroll
    for (int k = 0; k < 32; k++) {
        float xv[8], wv[8];
        *(float4*)&xv[0] = *(const float4*)&XsT[k][ty * 8];
        *(float4*)&xv[4] = *(const float4*)&XsT[k][ty * 8 + 4];
        *(float4*)&wv[0] = *(const float4*)&Ws [k][tx * 8];
        *(float4*)&wv[4] = *(const float4*)&Ws [k][tx * 8 + 4];
        #pragma unroll
        for (int i = 0; i < 8; i++)
            #pragma unroll
            for (int j = 0; j < 8; j++)
                acc[i][j] = fmaf(xv[i], wv[j], acc[i][j]);
    }
    __syncthreads();

    // ---- store prefetched stage 1 ----
    #pragma unroll
    for (int i = 0; i < 4; i++) {
        XsT[xkq[i] * 4 + 0][xrow[i]] = xr[i].x;
        XsT[xkq[i] * 4 + 1][xrow[i]] = xr[i].y;
        XsT[xkq[i] * 4 + 2][xrow[i]] = xr[i].z;
        XsT[xkq[i] * 4 + 3][xrow[i]] = xr[i].w;
        *(float4*)&Ws[wk[i]][wcq[i] * 4] = wr[i];
    }
    __syncthreads();

    // ---- compute kb=1 ----
    #pragma unroll
    for (int k = 0; k < 32; k++) {
        float xv[8], wv[8];
        *(float4*)&xv[0] = *(const float4*)&XsT[k][ty * 8];
        *(float4*)&xv[4] = *(const float4*)&XsT[k][ty * 8 + 4];
        *(float4*)&wv[0] = *(const float4*)&Ws [k][tx * 8];
        *(float4*)&wv[4] = *(const float4*)&Ws [k][tx * 8 + 4];
        #pragma unroll
        for (int i = 0; i < 8; i++)
            #pragma unroll
            for (int j = 0; j < 8; j++)
                acc[i][j] = fmaf(xv[i], wv[j], acc[i][j]);
    }

    // ---- epilogue: fold b1 into A-part; store ----
    if (part == 0) {
        float4 bb0 = *(const float4*)&b1[tx * 8];
        float4 bb1 = *(const float4*)&b1[tx * 8 + 4];
        #pragma unroll
        for (int i = 0; i < 8; i++) {
            acc[i][0] += bb0.x; acc[i][1] += bb0.y; acc[i][2] += bb0.z; acc[i][3] += bb0.w;
            acc[i][4] += bb1.x; acc[i][5] += bb1.y; acc[i][6] += bb1.z; acc[i][7] += bb1.w;
        }
    }
    #pragma unroll
    for (int i = 0; i < 8; i++) {
        float* dst = &g_ABC[(size_t)(m0 + ty * 8 + i) * ABC_COLS + part * DH + tx * 8];
        *(float4*)&dst[0] = make_float4(acc[i][0], acc[i][1], acc[i][2], acc[i][3]);
        *(float4*)&dst[4] = make_float4(acc[i][4], acc[i][5], acc[i][6], acc[i][7]);
    }
}

// ---------------------------------------------------------------------------
// Kernel 2: per token m (one warp each):
//   g = (1/S) * sum_s gelu( A[m](incl b1) + Bpart[j_s] + Cpart[k_s] )  (128)
//   out[m] = g @ W2 + b2                                                (64)
// Matvec uses W2 transposed in smem [o][k+pad] for wide conflict-free LDS.
// ---------------------------------------------------------------------------
__global__ __launch_bounds__(256) void k2_fused(const int* __restrict__ j_idx,
                                                const int* __restrict__ k_idx,
                                                const float* __restrict__ W2,
                                                const float* __restrict__ b2,
                                                float* __restrict__ out)
{
    __shared__ float w2Ts[DOUT][DH + 4];   // [o][k], row stride 132 floats
    __shared__ float b2s[DOUT];
    __shared__ float gbuf[8][DH + 4];      // per-warp g staging, stride 132

    const int tid = threadIdx.x;
    for (int i = tid; i < DH * DOUT; i += 256) {
        int k = i >> 6, o = i & 63;        // W2 row-major [k][o]
        w2Ts[o][k] = W2[i];
    }
    if (tid < DOUT) b2s[tid] = b2[tid];
    __syncthreads();

    const int warp = tid >> 5;
    const int lane = tid & 31;
    const int m    = blockIdx.x * 8 + warp;
    const int base = m & ~(NN - 1);        // b * N

    // a = A[m][lane*4 .. +3]  (b1 already folded in by k1)
    float4 a = *(const float4*)&g_ABC[(size_t)m * ABC_COLS + lane * 4];

    int4 j03 = *(const int4*)&j_idx[(size_t)m * SS];
    int4 j47 = *(const int4*)&j_idx[(size_t)m * SS + 4];
    int4 k03 = *(const int4*)&k_idx[(size_t)m * SS];
    int4 k47 = *(const int4*)&k_idx[(size_t)m * SS + 4];
    int js[8] = { j03.x, j03.y, j03.z, j03.w, j47.x, j47.y, j47.z, j47.w };
    int ks[8] = { k03.x, k03.y, k03.z, k03.w, k47.x, k47.y, k47.z, k47.w };

    float4 acc = make_float4(0.f, 0.f, 0.f, 0.f);
    #pragma unroll
    for (int s = 0; s < SS; s++) {
        const float* bp = &g_ABC[(size_t)(base + js[s]) * ABC_COLS + DH    + lane * 4];
        const float* cp = &g_ABC[(size_t)(base + ks[s]) * ABC_COLS + 2*DH  + lane * 4];
        float4 vb = *(const float4*)bp;
        float4 vc = *(const float4*)cp;
        acc.x += gelu_fast(a.x + vb.x + vc.x);
        acc.y += gelu_fast(a.y + vb.y + vc.y);
        acc.z += gelu_fast(a.z + vb.z + vc.z);
        acc.w += gelu_fast(a.w + vb.w + vc.w);
    }
    acc.x *= 0.125f; acc.y *= 0.125f; acc.z *= 0.125f; acc.w *= 0.125f;

    *(float4*)&gbuf[warp][lane * 4] = acc;
    __syncwarp();

    // out[m][o], o = lane and lane+32.  Per 4k: 1 bcast LDS.128 + 2 LDS.128 + 8 FMA.
    const int o = lane;
    float s0 = 0.f, s1 = 0.f;
    #pragma unroll
    for (int k = 0; k < DH; k += 4) {
        float4 g  = *(const float4*)&gbuf[warp][k];
        float4 wa = *(const float4*)&w2Ts[o][k];
        float4 wb = *(const float4*)&w2Ts[o + 32][k];
        s0 = fmaf(g.x, wa.x, s0); s0 = fmaf(g.y, wa.y, s0);
        s0 = fmaf(g.z, wa.z, s0); s0 = fmaf(g.w, wa.w, s0);
        s1 = fmaf(g.x, wb.x, s1); s1 = fmaf(g.y, wb.y, s1);
        s1 = fmaf(g.z, wb.z, s1); s1 = fmaf(g.w, wb.w, s1);
    }
    out[(size_t)m * DOUT + o]      = s0 + b2s[o];
    out[(size_t)m * DOUT + o + 32] = s1 + b2s[o + 32];
}

// ---------------------------------------------------------------------------
extern "C" void kernel_launch(void* const* d_in, const int* in_sizes, int n_in,
                              void* d_out, int out_size)
{
    const float* x     = (const float*)d_in[0];
    const int*   j_idx = (const int*)  d_in[1];
    const int*   k_idx = (const int*)  d_in[2];
    const float* W1    = (const float*)d_in[3];
    const float* b1    = (const float*)d_in[4];
    const float* W2    = (const float*)d_in[5];
    const float* b2    = (const float*)d_in[6];
    float*       out   = (float*)d_out;

    dim3 g1(MROWS / 128, 3);
    k1_gemm<<<g1, 256>>>(x, W1, b1);
    k2_fused<<<MROWS / 8, 256>>>(j_idx, k_idx, W2, b2, out);
}

// round 7
// speedup vs baseline: 1.3415x; 1.3415x over previous
#include <cuda_runtime.h>
#include <math.h>

#define BB 8
#define NN 8192
#define SS 8
#define MROWS (BB * NN)          // 65536 tokens
#define DIN 64
#define DH  128                  // hidden
#define DOUT 64
#define ABC_COLS 384             // [A(128) | B(128) | C(128)]

// Scratch: ABC[m][0:128]=x@W1a (+b1), [128:256]=x@W1b, [256:384]=x@W1c  (96 MB)
__device__ float g_ABC[(size_t)MROWS * ABC_COLS];
// Scratch: post-GELU averaged hidden g[m][0:128]  (32 MB)
__device__ float g_G[(size_t)MROWS * DH];

// tanh-form GELU with HW MUFU.TANH.
__device__ __forceinline__ float gelu_fast(float x) {
    float x2 = x * x;
    float u  = x * (0.7978845608028654f + 0.035677408136300125f * x2);
    float t;
    asm("tanh.approx.f32 %0, %1;" : "=f"(t) : "f"(u));
    return 0.5f * x * (1.0f + t);
}

// ---------------------------------------------------------------------------
// Kernel 1: ABC = X (65536 x 64) @ W1-as-(64 x 384)   [+ b1 on part 0]
// ---------------------------------------------------------------------------
__global__ __launch_bounds__(256, 2) void k1_gemm(const float* __restrict__ X,
                                                  const float* __restrict__ W1,
                                                  const float* __restrict__ b1)
{
    __shared__ float XsT[32][132];   // [k][row] transposed, padded
    __shared__ float Ws [32][128];   // [k][col_local]

    const int tid  = threadIdx.x;
    const int m0   = blockIdx.x * 128;
    const int part = blockIdx.y;           // 0..2

    int xrow[4], xkq[4];
    #pragma unroll
    for (int i = 0; i < 4; i++) {
        int lin = tid + i * 256;
        xrow[i] = lin >> 3;
        xkq[i]  = lin & 7;
        float4 v = *(const float4*)&X[(size_t)(m0 + xrow[i]) * DIN + xkq[i] * 4];
        XsT[xkq[i] * 4 + 0][xrow[i]] = v.x;
        XsT[xkq[i] * 4 + 1][xrow[i]] = v.y;
        XsT[xkq[i] * 4 + 2][xrow[i]] = v.z;
        XsT[xkq[i] * 4 + 3][xrow[i]] = v.w;
    }
    int wk[4], wcq[4];
    #pragma unroll
    for (int i = 0; i < 4; i++) {
        int lin = tid + i * 256;
        wk[i]  = lin >> 5;
        wcq[i] = lin & 31;
        *(float4*)&Ws[wk[i]][wcq[i] * 4] =
            *(const float4*)&W1[(size_t)(part * 64 + wk[i]) * DH + wcq[i] * 4];
    }

    // prefetch stage 1 (kb=1)
    float4 xr[4], wr[4];
    #pragma unroll
    for (int i = 0; i < 4; i++)
        xr[i] = *(const float4*)&X[(size_t)(m0 + xrow[i]) * DIN + 32 + xkq[i] * 4];
    #pragma unroll
    for (int i = 0; i < 4; i++)
        wr[i] = *(const float4*)&W1[(size_t)(part * 64 + 32 + wk[i]) * DH + wcq[i] * 4];

    __syncthreads();

    const int tx = tid & 15;
    const int ty = tid >> 4;
    float acc[8][8];
    #pragma unroll
    for (int i = 0; i < 8; i++)
        #pragma unroll
        for (int j = 0; j < 8; j++) acc[i][j] = 0.0f;

    #pragma unroll
    for (int k = 0; k < 32; k++) {
        float xv[8], wv[8];
        *(float4*)&xv[0] = *(const float4*)&XsT[k][ty * 8];
        *(float4*)&xv[4] = *(const float4*)&XsT[k][ty * 8 + 4];
        *(float4*)&wv[0] = *(const float4*)&Ws [k][tx * 8];
        *(float4*)&wv[4] = *(const float4*)&Ws [k][tx * 8 + 4];
        #pragma unroll
        for (int i = 0; i < 8; i++)
            #pragma unroll
            for (int j = 0; j < 8; j++)
                acc[i][j] = fmaf(xv[i], wv[j], acc[i][j]);
    }
    __syncthreads();

    #pragma unroll
    for (int i = 0; i < 4; i++) {
        XsT[xkq[i] * 4 + 0][xrow[i]] = xr[i].x;
        XsT[xkq[i] * 4 + 1][xrow[i]] = xr[i].y;
        XsT[xkq[i] * 4 + 2][xrow[i]] = xr[i].z;
        XsT[xkq[i] * 4 + 3][xrow[i]] = xr[i].w;
        *(float4*)&Ws[wk[i]][wcq[i] * 4] = wr[i];
    }
    __syncthreads();

    #pragma unroll
    for (int k = 0; k < 32; k++) {
        float xv[8], wv[8];
        *(float4*)&xv[0] = *(const float4*)&XsT[k][ty * 8];
        *(float4*)&xv[4] = *(const float4*)&XsT[k][ty * 8 + 4];
        *(float4*)&wv[0] = *(const float4*)&Ws [k][tx * 8];
        *(float4*)&wv[4] = *(const float4*)&Ws [k][tx * 8 + 4];
        #pragma unroll
        for (int i = 0; i < 8; i++)
            #pragma unroll
            for (int j = 0; j < 8; j++)
                acc[i][j] = fmaf(xv[i], wv[j], acc[i][j]);
    }

    if (part == 0) {
        float4 bb0 = *(const float4*)&b1[tx * 8];
        float4 bb1 = *(const float4*)&b1[tx * 8 + 4];
        #pragma unroll
        for (int i = 0; i < 8; i++) {
            acc[i][0] += bb0.x; acc[i][1] += bb0.y; acc[i][2] += bb0.z; acc[i][3] += bb0.w;
            acc[i][4] += bb1.x; acc[i][5] += bb1.y; acc[i][6] += bb1.z; acc[i][7] += bb1.w;
        }
    }
    #pragma unroll
    for (int i = 0; i < 8; i++) {
        float* dst = &g_ABC[(size_t)(m0 + ty * 8 + i) * ABC_COLS + part * DH + tx * 8];
        *(float4*)&dst[0] = make_float4(acc[i][0], acc[i][1], acc[i][2], acc[i][3]);
        *(float4*)&dst[4] = make_float4(acc[i][4], acc[i][5], acc[i][6], acc[i][7]);
    }
}

// ---------------------------------------------------------------------------
// Kernel 2: gather + GELU + mean only. One warp per token.
//   g[m] = (1/S) * sum_s gelu( A[m] + Bpart[j_s] + Cpart[k_s] )   (128-dim)
// No smem, no block sync — pure LDG/MUFU/STG.
// ---------------------------------------------------------------------------
__global__ __launch_bounds__(256, 6) void k2_gather(const int* __restrict__ j_idx,
                                                    const int* __restrict__ k_idx)
{
    const int tid  = threadIdx.x;
    const int warp = tid >> 5;
    const int lane = tid & 31;
    const int m    = blockIdx.x * 8 + warp;
    const int base = m & ~(NN - 1);        // b * N

    float4 a = *(const float4*)&g_ABC[(size_t)m * ABC_COLS + lane * 4];

    int4 j03 = *(const int4*)&j_idx[(size_t)m * SS];
    int4 j47 = *(const int4*)&j_idx[(size_t)m * SS + 4];
    int4 k03 = *(const int4*)&k_idx[(size_t)m * SS];
    int4 k47 = *(const int4*)&k_idx[(size_t)m * SS + 4];
    int js[8] = { j03.x, j03.y, j03.z, j03.w, j47.x, j47.y, j47.z, j47.w };
    int ks[8] = { k03.x, k03.y, k03.z, k03.w, k47.x, k47.y, k47.z, k47.w };

    float4 acc = make_float4(0.f, 0.f, 0.f, 0.f);
    #pragma unroll
    for (int s = 0; s < SS; s++) {
        float4 vb = *(const float4*)&g_ABC[(size_t)(base + js[s]) * ABC_COLS + DH   + lane * 4];
        float4 vc = *(const float4*)&g_ABC[(size_t)(base + ks[s]) * ABC_COLS + 2*DH + lane * 4];
        acc.x += gelu_fast(a.x + vb.x + vc.x);
        acc.y += gelu_fast(a.y + vb.y + vc.y);
        acc.z += gelu_fast(a.z + vb.z + vc.z);
        acc.w += gelu_fast(a.w + vb.w + vc.w);
    }
    acc.x *= 0.125f; acc.y *= 0.125f; acc.z *= 0.125f; acc.w *= 0.125f;

    *(float4*)&g_G[(size_t)m * DH + lane * 4] = acc;   // coalesced 512B per warp
}

// ---------------------------------------------------------------------------
// Kernel 3: OUT (65536 x 64) = G (65536 x 128) @ W2 (128 x 64) + b2
//   128-row tile, K=128 in 4 stages of 32, 8x4 register tile, 256 threads.
// ---------------------------------------------------------------------------
__global__ __launch_bounds__(256, 2) void k3_gemm(const float* __restrict__ W2,
                                                  const float* __restrict__ b2,
                                                  float* __restrict__ out)
{
    __shared__ float GsT[32][132];   // [k][row] transposed, padded  (16.5KB)
    __shared__ float W2s[32][64];    // [k][o]                        (8KB)

    const int tid = threadIdx.x;
    const int m0  = blockIdx.x * 128;
    const int tx  = tid & 15;        // o group: 16 x 4 = 64
    const int ty  = tid >> 4;        // row group: 16 x 8 = 128

    float acc[8][4];
    #pragma unroll
    for (int i = 0; i < 8; i++)
        #pragma unroll
        for (int j = 0; j < 4; j++) acc[i][j] = 0.0f;

    for (int ksg = 0; ksg < 4; ksg++) {
        // G slice: 128 rows x 32 k = 1024 float4, transpose
        #pragma unroll
        for (int i = 0; i < 4; i++) {
            int lin = tid + i * 256;
            int row = lin >> 3;
            int kq  = lin & 7;
            float4 v = *(const float4*)&g_G[(size_t)(m0 + row) * DH + ksg * 32 + kq * 4];
            GsT[kq * 4 + 0][row] = v.x;
            GsT[kq * 4 + 1][row] = v.y;
            GsT[kq * 4 + 2][row] = v.z;
            GsT[kq * 4 + 3][row] = v.w;
        }
        // W2 slice: 32 k x 64 o = 512 float4 / 256 threads = 2 each
        #pragma unroll
        for (int i = 0; i < 2; i++) {
            int lin = tid + i * 256;       // 0..511
            int k   = lin >> 4;            // 0..31
            int cq  = lin & 15;            // 0..15
            *(float4*)&W2s[k][cq * 4] =
                *(const float4*)&W2[(size_t)(ksg * 32 + k) * DOUT + cq * 4];
        }
        __syncthreads();

        #pragma unroll
        for (int k = 0; k < 32; k++) {
            float gv[8], wv[4];
            *(float4*)&gv[0] = *(const float4*)&GsT[k][ty * 8];
            *(float4*)&gv[4] = *(const float4*)&GsT[k][ty * 8 + 4];
            *(float4*)&wv[0] = *(const float4*)&W2s[k][tx * 4];
            #pragma unroll
            for (int i = 0; i < 8; i++)
                #pragma unroll
                for (int j = 0; j < 4; j++)
                    acc[i][j] = fmaf(gv[i], wv[j], acc[i][j]);
        }
        __syncthreads();
    }

    float4 bb = *(const float4*)&b2[tx * 4];
    #pragma unroll
    for (int i = 0; i < 8; i++) {
        float4 r = make_float4(acc[i][0] + bb.x, acc[i][1] + bb.y,
                               acc[i][2] + bb.z, acc[i][3] + bb.w);
        *(float4*)&out[(size_t)(m0 + ty * 8 + i) * DOUT + tx * 4] = r;
    }
}

// ---------------------------------------------------------------------------
extern "C" void kernel_launch(void* const* d_in, const int* in_sizes, int n_in,
                              void* d_out, int out_size)
{
    const float* x     = (const float*)d_in[0];
    const int*   j_idx = (const int*)  d_in[1];
    const int*   k_idx = (const int*)  d_in[2];
    const float* W1    = (const float*)d_in[3];
    const float* b1    = (const float*)d_in[4];
    const float* W2    = (const float*)d_in[5];
    const float* b2    = (const float*)d_in[6];
    float*       out   = (float*)d_out;

    dim3 g1(MROWS / 128, 3);
    k1_gemm<<<g1, 256>>>(x, W1, b1);
    k2_gather<<<MROWS / 8, 256>>>(j_idx, k_idx);
    k3_gemm<<<MROWS / 128, 256>>>(W2, b2, out);
}

// round 8
// speedup vs baseline: 1.4425x; 1.0753x over previous
#include <cuda_runtime.h>
#include <math.h>

#define BB 8
#define NN 8192
#define SS 8
#define MROWS (BB * NN)          // 65536 tokens
#define DIN 64
#define DH  128                  // hidden
#define DOUT 64
#define ABC_COLS 384             // [A(128) | B(128) | C(128)]

// Scratch: ABC[m][0:128]=x@W1a (+b1), [128:256]=x@W1b, [256:384]=x@W1c  (96 MB)
__device__ float g_ABC[(size_t)MROWS * ABC_COLS];
// Scratch: post-GELU averaged hidden g[m][0:128]  (32 MB)
__device__ float g_G[(size_t)MROWS * DH];

// tanh-form GELU with HW MUFU.TANH.
__device__ __forceinline__ float gelu_fast(float x) {
    float x2 = x * x;
    float u  = x * (0.7978845608028654f + 0.035677408136300125f * x2);
    float t;
    asm("tanh.approx.f32 %0, %1;" : "=f"(t) : "f"(u));
    return 0.5f * x * (1.0f + t);
}

// ---------------------------------------------------------------------------
// Kernel 1: ABC = X (65536 x 64) @ W1-as-(64 x 384)   [+ b1 on part 0]
//   Thread cols remapped to {tx*4..+3, 64+tx*4..+3}: Ws LDS.128 conflict-free.
// ---------------------------------------------------------------------------
__global__ __launch_bounds__(256, 2) void k1_gemm(const float* __restrict__ X,
                                                  const float* __restrict__ W1,
                                                  const float* __restrict__ b1)
{
    __shared__ float XsT[32][132];   // [k][row] transposed, padded
    __shared__ float Ws [32][128];   // [k][col_local]

    const int tid  = threadIdx.x;
    const int m0   = blockIdx.x * 128;
    const int part = blockIdx.y;           // 0..2

    int xrow[4], xkq[4];
    #pragma unroll
    for (int i = 0; i < 4; i++) {
        int lin = tid + i * 256;
        xrow[i] = lin >> 3;
        xkq[i]  = lin & 7;
        float4 v = *(const float4*)&X[(size_t)(m0 + xrow[i]) * DIN + xkq[i] * 4];
        XsT[xkq[i] * 4 + 0][xrow[i]] = v.x;
        XsT[xkq[i] * 4 + 1][xrow[i]] = v.y;
        XsT[xkq[i] * 4 + 2][xrow[i]] = v.z;
        XsT[xkq[i] * 4 + 3][xrow[i]] = v.w;
    }
    int wk[4], wcq[4];
    #pragma unroll
    for (int i = 0; i < 4; i++) {
        int lin = tid + i * 256;
        wk[i]  = lin >> 5;
        wcq[i] = lin & 31;
        *(float4*)&Ws[wk[i]][wcq[i] * 4] =
            *(const float4*)&W1[(size_t)(part * 64 + wk[i]) * DH + wcq[i] * 4];
    }

    // prefetch stage 1 (kb=1) into registers
    float4 xr[4], wr[4];
    #pragma unroll
    for (int i = 0; i < 4; i++)
        xr[i] = *(const float4*)&X[(size_t)(m0 + xrow[i]) * DIN + 32 + xkq[i] * 4];
    #pragma unroll
    for (int i = 0; i < 4; i++)
        wr[i] = *(const float4*)&W1[(size_t)(part * 64 + 32 + wk[i]) * DH + wcq[i] * 4];

    __syncthreads();

    const int tx = tid & 15;
    const int ty = tid >> 4;
    float acc[8][8];                       // [row i][j: 0-3 -> col tx*4+j, 4-7 -> col 64+tx*4+j-4]
    #pragma unroll
    for (int i = 0; i < 8; i++)
        #pragma unroll
        for (int j = 0; j < 8; j++) acc[i][j] = 0.0f;

    #pragma unroll
    for (int k = 0; k < 32; k++) {
        float xv[8], wv[8];
        *(float4*)&xv[0] = *(const float4*)&XsT[k][ty * 8];
        *(float4*)&xv[4] = *(const float4*)&XsT[k][ty * 8 + 4];
        *(float4*)&wv[0] = *(const float4*)&Ws [k][tx * 4];        // conflict-free
        *(float4*)&wv[4] = *(const float4*)&Ws [k][64 + tx * 4];   // conflict-free
        #pragma unroll
        for (int i = 0; i < 8; i++)
            #pragma unroll
            for (int j = 0; j < 8; j++)
                acc[i][j] = fmaf(xv[i], wv[j], acc[i][j]);
    }
    __syncthreads();

    #pragma unroll
    for (int i = 0; i < 4; i++) {
        XsT[xkq[i] * 4 + 0][xrow[i]] = xr[i].x;
        XsT[xkq[i] * 4 + 1][xrow[i]] = xr[i].y;
        XsT[xkq[i] * 4 + 2][xrow[i]] = xr[i].z;
        XsT[xkq[i] * 4 + 3][xrow[i]] = xr[i].w;
        *(float4*)&Ws[wk[i]][wcq[i] * 4] = wr[i];
    }
    __syncthreads();

    #pragma unroll
    for (int k = 0; k < 32; k++) {
        float xv[8], wv[8];
        *(float4*)&xv[0] = *(const float4*)&XsT[k][ty * 8];
        *(float4*)&xv[4] = *(const float4*)&XsT[k][ty * 8 + 4];
        *(float4*)&wv[0] = *(const float4*)&Ws [k][tx * 4];
        *(float4*)&wv[4] = *(const float4*)&Ws [k][64 + tx * 4];
        #pragma unroll
        for (int i = 0; i < 8; i++)
            #pragma unroll
            for (int j = 0; j < 8; j++)
                acc[i][j] = fmaf(xv[i], wv[j], acc[i][j]);
    }

    if (part == 0) {
        float4 bb0 = *(const float4*)&b1[tx * 4];
        float4 bb1 = *(const float4*)&b1[64 + tx * 4];
        #pragma unroll
        for (int i = 0; i < 8; i++) {
            acc[i][0] += bb0.x; acc[i][1] += bb0.y; acc[i][2] += bb0.z; acc[i][3] += bb0.w;
            acc[i][4] += bb1.x; acc[i][5] += bb1.y; acc[i][6] += bb1.z; acc[i][7] += bb1.w;
        }
    }
    #pragma unroll
    for (int i = 0; i < 8; i++) {
        float* dst = &g_ABC[(size_t)(m0 + ty * 8 + i) * ABC_COLS + part * DH];
        *(float4*)&dst[tx * 4]      = make_float4(acc[i][0], acc[i][1], acc[i][2], acc[i][3]);
        *(float4*)&dst[64 + tx * 4] = make_float4(acc[i][4], acc[i][5], acc[i][6], acc[i][7]);
    }
}

// ---------------------------------------------------------------------------
// Kernel 2: gather + GELU + mean only. One warp per token.
// ---------------------------------------------------------------------------
__global__ __launch_bounds__(256, 6) void k2_gather(const int* __restrict__ j_idx,
                                                    const int* __restrict__ k_idx)
{
    const int tid  = threadIdx.x;
    const int warp = tid >> 5;
    const int lane = tid & 31;
    const int m    = blockIdx.x * 8 + warp;
    const int base = m & ~(NN - 1);        // b * N

    float4 a = *(const float4*)&g_ABC[(size_t)m * ABC_COLS + lane * 4];

    int4 j03 = *(const int4*)&j_idx[(size_t)m * SS];
    int4 j47 = *(const int4*)&j_idx[(size_t)m * SS + 4];
    int4 k03 = *(const int4*)&k_idx[(size_t)m * SS];
    int4 k47 = *(const int4*)&k_idx[(size_t)m * SS + 4];
    int js[8] = { j03.x, j03.y, j03.z, j03.w, j47.x, j47.y, j47.z, j47.w };
    int ks[8] = { k03.x, k03.y, k03.z, k03.w, k47.x, k47.y, k47.z, k47.w };

    float4 acc = make_float4(0.f, 0.f, 0.f, 0.f);
    #pragma unroll
    for (int s = 0; s < SS; s++) {
        float4 vb = *(const float4*)&g_ABC[(size_t)(base + js[s]) * ABC_COLS + DH   + lane * 4];
        float4 vc = *(const float4*)&g_ABC[(size_t)(base + ks[s]) * ABC_COLS + 2*DH + lane * 4];
        acc.x += gelu_fast(a.x + vb.x + vc.x);
        acc.y += gelu_fast(a.y + vb.y + vc.y);
        acc.z += gelu_fast(a.z + vb.z + vc.z);
        acc.w += gelu_fast(a.w + vb.w + vc.w);
    }
    acc.x *= 0.125f; acc.y *= 0.125f; acc.z *= 0.125f; acc.w *= 0.125f;

    *(float4*)&g_G[(size_t)m * DH + lane * 4] = acc;   // coalesced 512B per warp
}

// ---------------------------------------------------------------------------
// Kernel 3: OUT (65536 x 64) = G (65536 x 128) @ W2 (128 x 64) + b2
// ---------------------------------------------------------------------------
__global__ __launch_bounds__(256, 2) void k3_gemm(const float* __restrict__ W2,
                                                  const float* __restrict__ b2,
                                                  float* __restrict__ out)
{
    __shared__ float GsT[32][132];   // [k][row] transposed, padded
    __shared__ float W2s[32][64];    // [k][o]

    const int tid = threadIdx.x;
    const int m0  = blockIdx.x * 128;
    const int tx  = tid & 15;        // o group: 16 x 4 = 64
    const int ty  = tid >> 4;        // row group: 16 x 8 = 128

    float acc[8][4];
    #pragma unroll
    for (int i = 0; i < 8; i++)
        #pragma unroll
        for (int j = 0; j < 4; j++) acc[i][j] = 0.0f;

    for (int ksg = 0; ksg < 4; ksg++) {
        #pragma unroll
        for (int i = 0; i < 4; i++) {
            int lin = tid + i * 256;
            int row = lin >> 3;
            int kq  = lin & 7;
            float4 v = *(const float4*)&g_G[(size_t)(m0 + row) * DH + ksg * 32 + kq * 4];
            GsT[kq * 4 + 0][row] = v.x;
            GsT[kq * 4 + 1][row] = v.y;
            GsT[kq * 4 + 2][row] = v.z;
            GsT[kq * 4 + 3][row] = v.w;
        }
        #pragma unroll
        for (int i = 0; i < 2; i++) {
            int lin = tid + i * 256;       // 0..511
            int k   = lin >> 4;            // 0..31
            int cq  = lin & 15;            // 0..15
            *(float4*)&W2s[k][cq * 4] =
                *(const float4*)&W2[(size_t)(ksg * 32 + k) * DOUT + cq * 4];
        }
        __syncthreads();

        #pragma unroll
        for (int k = 0; k < 32; k++) {
            float gv[8], wv[4];
            *(float4*)&gv[0] = *(const float4*)&GsT[k][ty * 8];
            *(float4*)&gv[4] = *(const float4*)&GsT[k][ty * 8 + 4];
            *(float4*)&wv[0] = *(const float4*)&W2s[k][tx * 4];
            #pragma unroll
            for (int i = 0; i < 8; i++)
                #pragma unroll
                for (int j = 0; j < 4; j++)
                    acc[i][j] = fmaf(gv[i], wv[j], acc[i][j]);
        }
        __syncthreads();
    }

    float4 bb = *(const float4*)&b2[tx * 4];
    #pragma unroll
    for (int i = 0; i < 8; i++) {
        float4 r = make_float4(acc[i][0] + bb.x, acc[i][1] + bb.y,
                               acc[i][2] + bb.z, acc[i][3] + bb.w);
        *(float4*)&out[(size_t)(m0 + ty * 8 + i) * DOUT + tx * 4] = r;
    }
}

// ---------------------------------------------------------------------------
extern "C" void kernel_launch(void* const* d_in, const int* in_sizes, int n_in,
                              void* d_out, int out_size)
{
    const float* x     = (const float*)d_in[0];
    const int*   j_idx = (const int*)  d_in[1];
    const int*   k_idx = (const int*)  d_in[2];
    const float* W1    = (const float*)d_in[3];
    const float* b1    = (const float*)d_in[4];
    const float* W2    = (const float*)d_in[5];
    const float* b2    = (const float*)d_in[6];
    float*       out   = (float*)d_out;

    dim3 g1(MROWS / 128, 3);
    k1_gemm<<<g1, 256>>>(x, W1, b1);
    k2_gather<<<MROWS / 8, 256>>>(j_idx, k_idx);
    k3_gemm<<<MROWS / 128, 256>>>(W2, b2, out);
}

// round 9
// speedup vs baseline: 1.5321x; 1.0621x over previous
#include <cuda_runtime.h>
#include <math.h>

#define BB 8
#define NN 8192
#define SS 8
#define MROWS (BB * NN)          // 65536 tokens
#define DIN 64
#define DH  128                  // hidden
#define DOUT 64
#define ABC_COLS 384             // [A(128) | B(128) | C(128)]

// Scratch: ABC[m][0:128]=x@W1a (+b1), [128:256]=x@W1b, [256:384]=x@W1c  (96 MB)
__device__ float g_ABC[(size_t)MROWS * ABC_COLS];
// Scratch: post-GELU averaged hidden g[m][0:128]  (32 MB)
__device__ float g_G[(size_t)MROWS * DH];

typedef unsigned long long u64;

// --- packed f32x2 helpers (Blackwell PTX; per-lane identical to scalar fmaf) ---
__device__ __forceinline__ u64 pack2(float x) {
    u64 r; unsigned int u = __float_as_uint(x);
    asm("mov.b64 %0, {%1, %1};" : "=l"(r) : "r"(u));
    return r;
}
__device__ __forceinline__ void ffma2(u64& d, u64 a, u64 b) {
    asm("fma.rn.f32x2 %0, %1, %2, %0;" : "+l"(d) : "l"(a), "l"(b));
}
__device__ __forceinline__ void addf2(u64& d, u64 b) {
    asm("add.rn.f32x2 %0, %0, %1;" : "+l"(d) : "l"(b));
}

// tanh-form GELU with HW MUFU.TANH.
__device__ __forceinline__ float gelu_fast(float x) {
    float x2 = x * x;
    float u  = x * (0.7978845608028654f + 0.035677408136300125f * x2);
    float t;
    asm("tanh.approx.f32 %0, %1;" : "=f"(t) : "f"(u));
    return 0.5f * x * (1.0f + t);
}

// ---------------------------------------------------------------------------
// Kernel 1: ABC = X (65536 x 64) @ W1-as-(64 x 384)   [+ b1 on part 0]
//   f32x2-packed mainloop: 32 FFMA2 + 8 packs per k vs 64 FFMA.
// ---------------------------------------------------------------------------
__global__ __launch_bounds__(256, 2) void k1_gemm(const float* __restrict__ X,
                                                  const float* __restrict__ W1,
                                                  const float* __restrict__ b1)
{
    __shared__ float XsT[32][132];   // [k][row] transposed, padded
    __shared__ float Ws [32][128];   // [k][col_local]

    const int tid  = threadIdx.x;
    const int m0   = blockIdx.x * 128;
    const int part = blockIdx.y;           // 0..2

    int xrow[4], xkq[4];
    #pragma unroll
    for (int i = 0; i < 4; i++) {
        int lin = tid + i * 256;
        xrow[i] = lin >> 3;
        xkq[i]  = lin & 7;
        float4 v = *(const float4*)&X[(size_t)(m0 + xrow[i]) * DIN + xkq[i] * 4];
        XsT[xkq[i] * 4 + 0][xrow[i]] = v.x;
        XsT[xkq[i] * 4 + 1][xrow[i]] = v.y;
        XsT[xkq[i] * 4 + 2][xrow[i]] = v.z;
        XsT[xkq[i] * 4 + 3][xrow[i]] = v.w;
    }
    int wk[4], wcq[4];
    #pragma unroll
    for (int i = 0; i < 4; i++) {
        int lin = tid + i * 256;
        wk[i]  = lin >> 5;
        wcq[i] = lin & 31;
        *(float4*)&Ws[wk[i]][wcq[i] * 4] =
            *(const float4*)&W1[(size_t)(part * 64 + wk[i]) * DH + wcq[i] * 4];
    }

    // prefetch stage 1 (kb=1) into registers
    float4 xr[4], wr[4];
    #pragma unroll
    for (int i = 0; i < 4; i++)
        xr[i] = *(const float4*)&X[(size_t)(m0 + xrow[i]) * DIN + 32 + xkq[i] * 4];
    #pragma unroll
    for (int i = 0; i < 4; i++)
        wr[i] = *(const float4*)&W1[(size_t)(part * 64 + 32 + wk[i]) * DH + wcq[i] * 4];

    __syncthreads();

    const int tx = tid & 15;
    const int ty = tid >> 4;
    // acc[i][p]: row ty*8+i; p=0,1 -> cols tx*4 + {0,1},{2,3}; p=2,3 -> cols 64+tx*4 + {0,1},{2,3}
    u64 acc[8][4];
    #pragma unroll
    for (int i = 0; i < 8; i++)
        #pragma unroll
        for (int p = 0; p < 4; p++) acc[i][p] = 0ULL;

    #pragma unroll
    for (int k = 0; k < 32; k++) {
        float xv[8];
        *(float4*)&xv[0] = *(const float4*)&XsT[k][ty * 8];
        *(float4*)&xv[4] = *(const float4*)&XsT[k][ty * 8 + 4];
        ulonglong2 w01 = *(const ulonglong2*)&Ws[k][tx * 4];        // conflict-free LDS.128
        ulonglong2 w23 = *(const ulonglong2*)&Ws[k][64 + tx * 4];   // conflict-free LDS.128
        #pragma unroll
        for (int i = 0; i < 8; i++) {
            u64 xp = pack2(xv[i]);
            ffma2(acc[i][0], xp, w01.x);
            ffma2(acc[i][1], xp, w01.y);
            ffma2(acc[i][2], xp, w23.x);
            ffma2(acc[i][3], xp, w23.y);
        }
    }
    __syncthreads();

    #pragma unroll
    for (int i = 0; i < 4; i++) {
        XsT[xkq[i] * 4 + 0][xrow[i]] = xr[i].x;
        XsT[xkq[i] * 4 + 1][xrow[i]] = xr[i].y;
        XsT[xkq[i] * 4 + 2][xrow[i]] = xr[i].z;
        XsT[xkq[i] * 4 + 3][xrow[i]] = xr[i].w;
        *(float4*)&Ws[wk[i]][wcq[i] * 4] = wr[i];
    }
    __syncthreads();

    #pragma unroll
    for (int k = 0; k < 32; k++) {
        float xv[8];
        *(float4*)&xv[0] = *(const float4*)&XsT[k][ty * 8];
        *(float4*)&xv[4] = *(const float4*)&XsT[k][ty * 8 + 4];
        ulonglong2 w01 = *(const ulonglong2*)&Ws[k][tx * 4];
        ulonglong2 w23 = *(const ulonglong2*)&Ws[k][64 + tx * 4];
        #pragma unroll
        for (int i = 0; i < 8; i++) {
            u64 xp = pack2(xv[i]);
            ffma2(acc[i][0], xp, w01.x);
            ffma2(acc[i][1], xp, w01.y);
            ffma2(acc[i][2], xp, w23.x);
            ffma2(acc[i][3], xp, w23.y);
        }
    }

    if (part == 0) {
        ulonglong2 bb0 = *(const ulonglong2*)&b1[tx * 4];
        ulonglong2 bb1 = *(const ulonglong2*)&b1[64 + tx * 4];
        #pragma unroll
        for (int i = 0; i < 8; i++) {
            addf2(acc[i][0], bb0.x); addf2(acc[i][1], bb0.y);
            addf2(acc[i][2], bb1.x); addf2(acc[i][3], bb1.y);
        }
    }
    #pragma unroll
    for (int i = 0; i < 8; i++) {
        float* dst = &g_ABC[(size_t)(m0 + ty * 8 + i) * ABC_COLS + part * DH];
        *(ulonglong2*)&dst[tx * 4]      = make_ulonglong2(acc[i][0], acc[i][1]);
        *(ulonglong2*)&dst[64 + tx * 4] = make_ulonglong2(acc[i][2], acc[i][3]);
    }
}

// ---------------------------------------------------------------------------
// Kernel 2: gather + GELU + mean only. One warp per token.
// ---------------------------------------------------------------------------
__global__ __launch_bounds__(256, 6) void k2_gather(const int* __restrict__ j_idx,
                                                    const int* __restrict__ k_idx)
{
    const int tid  = threadIdx.x;
    const int warp = tid >> 5;
    const int lane = tid & 31;
    const int m    = blockIdx.x * 8 + warp;
    const int base = m & ~(NN - 1);        // b * N

    float4 a = *(const float4*)&g_ABC[(size_t)m * ABC_COLS + lane * 4];

    int4 j03 = *(const int4*)&j_idx[(size_t)m * SS];
    int4 j47 = *(const int4*)&j_idx[(size_t)m * SS + 4];
    int4 k03 = *(const int4*)&k_idx[(size_t)m * SS];
    int4 k47 = *(const int4*)&k_idx[(size_t)m * SS + 4];
    int js[8] = { j03.x, j03.y, j03.z, j03.w, j47.x, j47.y, j47.z, j47.w };
    int ks[8] = { k03.x, k03.y, k03.z, k03.w, k47.x, k47.y, k47.z, k47.w };

    float4 acc = make_float4(0.f, 0.f, 0.f, 0.f);
    #pragma unroll
    for (int s = 0; s < SS; s++) {
        float4 vb = *(const float4*)&g_ABC[(size_t)(base + js[s]) * ABC_COLS + DH   + lane * 4];
        float4 vc = *(const float4*)&g_ABC[(size_t)(base + ks[s]) * ABC_COLS + 2*DH + lane * 4];
        acc.x += gelu_fast(a.x + vb.x + vc.x);
        acc.y += gelu_fast(a.y + vb.y + vc.y);
        acc.z += gelu_fast(a.z + vb.z + vc.z);
        acc.w += gelu_fast(a.w + vb.w + vc.w);
    }
    acc.x *= 0.125f; acc.y *= 0.125f; acc.z *= 0.125f; acc.w *= 0.125f;

    *(float4*)&g_G[(size_t)m * DH + lane * 4] = acc;   // coalesced 512B per warp
}

// ---------------------------------------------------------------------------
// Kernel 3: OUT (65536 x 64) = G (65536 x 128) @ W2 (128 x 64) + b2
//   f32x2-packed mainloop.
// ---------------------------------------------------------------------------
__global__ __launch_bounds__(256, 2) void k3_gemm(const float* __restrict__ W2,
                                                  const float* __restrict__ b2,
                                                  float* __restrict__ out)
{
    __shared__ float GsT[32][132];   // [k][row] transposed, padded
    __shared__ float W2s[32][64];    // [k][o]

    const int tid = threadIdx.x;
    const int m0  = blockIdx.x * 128;
    const int tx  = tid & 15;        // o group: 16 x 4 = 64
    const int ty  = tid >> 4;        // row group: 16 x 8 = 128

    u64 acc[8][2];
    #pragma unroll
    for (int i = 0; i < 8; i++) { acc[i][0] = 0ULL; acc[i][1] = 0ULL; }

    for (int ksg = 0; ksg < 4; ksg++) {
        #pragma unroll
        for (int i = 0; i < 4; i++) {
            int lin = tid + i * 256;
            int row = lin >> 3;
            int kq  = lin & 7;
            float4 v = *(const float4*)&g_G[(size_t)(m0 + row) * DH + ksg * 32 + kq * 4];
            GsT[kq * 4 + 0][row] = v.x;
            GsT[kq * 4 + 1][row] = v.y;
            GsT[kq * 4 + 2][row] = v.z;
            GsT[kq * 4 + 3][row] = v.w;
        }
        #pragma unroll
        for (int i = 0; i < 2; i++) {
            int lin = tid + i * 256;       // 0..511
            int k   = lin >> 4;            // 0..31
            int cq  = lin & 15;            // 0..15
            *(float4*)&W2s[k][cq * 4] =
                *(const float4*)&W2[(size_t)(ksg * 32 + k) * DOUT + cq * 4];
        }
        __syncthreads();

        #pragma unroll
        for (int k = 0; k < 32; k++) {
            float gv[8];
            *(float4*)&gv[0] = *(const float4*)&GsT[k][ty * 8];
            *(float4*)&gv[4] = *(const float4*)&GsT[k][ty * 8 + 4];
            ulonglong2 w = *(const ulonglong2*)&W2s[k][tx * 4];
            #pragma unroll
            for (int i = 0; i < 8; i++) {
                u64 gp = pack2(gv[i]);
                ffma2(acc[i][0], gp, w.x);
                ffma2(acc[i][1], gp, w.y);
            }
        }
        __syncthreads();
    }

    ulonglong2 bb = *(const ulonglong2*)&b2[tx * 4];
    #pragma unroll
    for (int i = 0; i < 8; i++) {
        addf2(acc[i][0], bb.x);
        addf2(acc[i][1], bb.y);
        *(ulonglong2*)&out[(size_t)(m0 + ty * 8 + i) * DOUT + tx * 4] =
            make_ulonglong2(acc[i][0], acc[i][1]);
    }
}

// ---------------------------------------------------------------------------
extern "C" void kernel_launch(void* const* d_in, const int* in_sizes, int n_in,
                              void* d_out, int out_size)
{
    const float* x     = (const float*)d_in[0];
    const int*   j_idx = (const int*)  d_in[1];
    const int*   k_idx = (const int*)  d_in[2];
    const float* W1    = (const float*)d_in[3];
    const float* b1    = (const float*)d_in[4];
    const float* W2    = (const float*)d_in[5];
    const float* b2    = (const float*)d_in[6];
    float*       out   = (float*)d_out;

    dim3 g1(MROWS / 128, 3);
    k1_gemm<<<g1, 256>>>(x, W1, b1);
    k2_gather<<<MROWS / 8, 256>>>(j_idx, k_idx);
    k3_gemm<<<MROWS / 128, 256>>>(W2, b2, out);
}